// round 3
// baseline (speedup 1.0000x reference)
#include <cuda_runtime.h>

#define BB   32
#define TT   128
#define KD   32
#define HH   4
#define DINP 160
#define HIDN 256

// Scratch (static device globals; no allocation).
__device__ float g_qT[BB * HH * KD * TT];   // [b][h][kk][i]  2MB
__device__ float g_kT[BB * HH * KD * TT];   // [b][h][kk][j]
__device__ float g_vT[BB * HH * KD * TT];   // [b][h][d][j]
__device__ float g_act[BB * TT * DINP];     // [x | state]  4096 x 160
__device__ float g_h1[BB * TT * HIDN];      // hidden1     4096 x 256

typedef unsigned long long ull;

__device__ __forceinline__ ull ffma2(ull a, ull b, ull c) {
    ull d;
    asm("fma.rn.f32x2 %0, %1, %2, %3;" : "=l"(d) : "l"(a), "l"(b), "l"(c));
    return d;
}
__device__ __forceinline__ ull pack2(float x, float y) {
    ull r;
    asm("mov.b64 %0, {%1, %2};" : "=l"(r) : "f"(x), "f"(y));
    return r;
}
__device__ __forceinline__ float2 unpack2(ull v) {
    float x, y;
    asm("mov.b64 {%0, %1}, %2;" : "=f"(x), "=f"(y) : "l"(v));
    return make_float2(x, y);
}

// ---------------------------------------------------------------------------
// Kernel 0: projections with transposed output.
// grid 384: blockIdx = rb (128 row-blocks of 32) + mat*128.
// ---------------------------------------------------------------------------
__global__ void __launch_bounds__(256) proj_kernel(
    const float* __restrict__ state,
    const float* __restrict__ Wq,
    const float* __restrict__ Wk,
    const float* __restrict__ Wv)
{
    __shared__ float sT[KD][36];       // stateT tile [c][r]
    __shared__ float Ws[KD * 128];     // W rows [k][c]

    const int bx  = blockIdx.x;
    const int rb  = bx & 127;
    const int mat = bx >> 7;
    const float* W = (mat == 0) ? Wq : (mat == 1) ? Wk : Wv;
    float* dstBase = (mat == 0) ? g_qT : (mat == 1) ? g_kT : g_vT;
    const int row0 = rb * 32;
    const int t = threadIdx.x;

    {   // stage W (32x128)
        const float4* src = (const float4*)W;
        float4* dst = (float4*)Ws;
        #pragma unroll
        for (int n = t; n < KD * 128 / 4; n += 256) dst[n] = src[n];
    }
    {   // stage state tile transposed
        int r = t >> 3, c0 = (t & 7) * 4;
        float4 v = *(const float4*)(state + (size_t)(row0 + r) * KD + c0);
        sT[c0 + 0][r] = v.x; sT[c0 + 1][r] = v.y;
        sT[c0 + 2][r] = v.z; sT[c0 + 3][r] = v.w;
    }
    __syncthreads();

    const int rg = t >> 5, cg = t & 31;
    const int r0 = rg * 4, c0 = cg * 4;
    ull acc[4][2];
    #pragma unroll
    for (int r = 0; r < 4; r++) { acc[r][0] = 0ull; acc[r][1] = 0ull; }

    #pragma unroll 8
    for (int k = 0; k < KD; k++) {
        float4 a4 = *(const float4*)&sT[k][r0];
        ulonglong2 b2 = *(const ulonglong2*)(Ws + k * 128 + c0);
        ull ad;
        ad = pack2(a4.x, a4.x); acc[0][0] = ffma2(ad, b2.x, acc[0][0]); acc[0][1] = ffma2(ad, b2.y, acc[0][1]);
        ad = pack2(a4.y, a4.y); acc[1][0] = ffma2(ad, b2.x, acc[1][0]); acc[1][1] = ffma2(ad, b2.y, acc[1][1]);
        ad = pack2(a4.z, a4.z); acc[2][0] = ffma2(ad, b2.x, acc[2][0]); acc[2][1] = ffma2(ad, b2.y, acc[2][1]);
        ad = pack2(a4.w, a4.w); acc[3][0] = ffma2(ad, b2.x, acc[3][0]); acc[3][1] = ffma2(ad, b2.y, acc[3][1]);
    }

    // transposed store
    const int b  = row0 >> 7;
    const int i0 = (row0 & 127) + r0;
    float cs[4][4];
    #pragma unroll
    for (int r = 0; r < 4; r++) {
        float2 p0 = unpack2(acc[r][0]), p1 = unpack2(acc[r][1]);
        cs[r][0] = p0.x; cs[r][1] = p0.y; cs[r][2] = p1.x; cs[r][3] = p1.y;
    }
    #pragma unroll
    for (int cc = 0; cc < 4; cc++) {
        int c = c0 + cc;
        int h = c >> 5, kk = c & 31;
        float4 o = make_float4(cs[0][cc], cs[1][cc], cs[2][cc], cs[3][cc]);
        *(float4*)(dstBase + ((size_t)((b * HH + h) * KD + kk)) * TT + i0) = o;
    }
}

// ---------------------------------------------------------------------------
// Kernel 1: masked attention for 64 query rows of one (b,h).
// grid 256 = (b, h, ihalf). Scores transposed in smem P[j][i].
// ---------------------------------------------------------------------------
__global__ void __launch_bounds__(256, 2) attn_kernel(const float* __restrict__ state)
{
    __shared__ float P[TT * 64];       // [j][i]  32KB
    __shared__ float s_mx[4][64];
    __shared__ float s_sm[4][64];
    __shared__ float s_inv[64];

    const int bx = blockIdx.x;
    const int b = bx >> 3, h = (bx >> 1) & 3, ihalf = bx & 1;
    const int t = threadIdx.x;
    const int ig0 = ihalf * 64;
    const float* QT = g_qT + (size_t)((b * HH + h) * KD) * TT;
    const float* KT = g_kT + (size_t)((b * HH + h) * KD) * TT;
    const float* VT = g_vT + (size_t)((b * HH + h) * KD) * TT;

    // ---- GEMM1: S^T[j][i] = K[j]·Q[i]; tile 8i x 4j
    {
        const int ig = t >> 5, jg = t & 31;
        const int i0 = ig * 8, j0 = jg * 4;
        ull acc[4][4];
        #pragma unroll
        for (int c = 0; c < 4; c++)
            #pragma unroll
            for (int p = 0; p < 4; p++) acc[c][p] = 0ull;

        #pragma unroll 4
        for (int kk = 0; kk < KD; kk++) {
            const float* qrow = QT + kk * TT + ig0 + i0;
            ulonglong2 a01 = *(const ulonglong2*)qrow;
            ulonglong2 a23 = *(const ulonglong2*)(qrow + 4);
            float4 bj = *(const float4*)(KT + kk * TT + j0);
            ull bd;
            bd = pack2(bj.x, bj.x);
            acc[0][0] = ffma2(bd, a01.x, acc[0][0]); acc[0][1] = ffma2(bd, a01.y, acc[0][1]);
            acc[0][2] = ffma2(bd, a23.x, acc[0][2]); acc[0][3] = ffma2(bd, a23.y, acc[0][3]);
            bd = pack2(bj.y, bj.y);
            acc[1][0] = ffma2(bd, a01.x, acc[1][0]); acc[1][1] = ffma2(bd, a01.y, acc[1][1]);
            acc[1][2] = ffma2(bd, a23.x, acc[1][2]); acc[1][3] = ffma2(bd, a23.y, acc[1][3]);
            bd = pack2(bj.z, bj.z);
            acc[2][0] = ffma2(bd, a01.x, acc[2][0]); acc[2][1] = ffma2(bd, a01.y, acc[2][1]);
            acc[2][2] = ffma2(bd, a23.x, acc[2][2]); acc[2][3] = ffma2(bd, a23.y, acc[2][3]);
            bd = pack2(bj.w, bj.w);
            acc[3][0] = ffma2(bd, a01.x, acc[3][0]); acc[3][1] = ffma2(bd, a01.y, acc[3][1]);
            acc[3][2] = ffma2(bd, a23.x, acc[3][2]); acc[3][3] = ffma2(bd, a23.y, acc[3][3]);
        }

        #pragma unroll
        for (int c = 0; c < 4; c++) {
            int jglob = j0 + c;
            int rd = jglob - ig0 - i0;          // diag position within my 8 i's
            if (rd >= 0 && rd < 8) {
                int p = rd >> 1, hi = rd & 1;
                float2 v = unpack2(acc[c][p]);
                if (hi) v.y = -1e30f; else v.x = -1e30f;
                acc[c][p] = pack2(v.x, v.y);
            }
            ull* dst = (ull*)&P[jglob * 64 + i0];
            dst[0] = acc[c][0]; dst[1] = acc[c][1];
            dst[2] = acc[c][2]; dst[3] = acc[c][3];
        }
    }
    __syncthreads();

    // ---- softmax (over j) on P, in place
    {
        const float scale = 0.17677669529663687f;   // 1/sqrt(32)
        const int i = t & 63, q = t >> 6;
        float mx = -1e30f;
        #pragma unroll 8
        for (int jj = 0; jj < 32; jj++)
            mx = fmaxf(mx, P[(q * 32 + jj) * 64 + i]);
        s_mx[q][i] = mx;
        __syncthreads();
        float m = fmaxf(fmaxf(s_mx[0][i], s_mx[1][i]), fmaxf(s_mx[2][i], s_mx[3][i]));
        float sum = 0.f;
        #pragma unroll 8
        for (int jj = 0; jj < 32; jj++) {
            int idx = (q * 32 + jj) * 64 + i;
            float e = __expf((P[idx] - m) * scale);
            P[idx] = e;
            sum += e;
        }
        s_sm[q][i] = sum;
    }
    // state copy into concat tail (no smem dependency)
    {
        #pragma unroll
        for (int n2 = t; n2 < 512; n2 += 256) {
            int r = n2 >> 3, c = n2 & 7;
            size_t row = (size_t)b * TT + ig0 + r;
            g_act[row * DINP + 4 * KD + h * 8 + c] = state[row * KD + h * 8 + c];
        }
    }
    __syncthreads();
    if (t < 64)
        s_inv[t] = 1.f / (s_sm[0][t] + s_sm[1][t] + s_sm[2][t] + s_sm[3][t]);
    __syncthreads();

    // ---- GEMM2: O[i][d] = sum_j P[j][i] * V[j][d]; tile 4i x 2d
    {
        const int ig = t & 15, dg = t >> 4;
        const int i0 = ig * 4, d0 = dg * 2;
        ull o[2][2];
        o[0][0] = 0ull; o[0][1] = 0ull; o[1][0] = 0ull; o[1][1] = 0ull;
        const float* v0p = VT + (size_t)d0 * TT;
        const float* v1p = VT + (size_t)(d0 + 1) * TT;

        #pragma unroll 4
        for (int j = 0; j < TT; j++) {
            ulonglong2 a = *(const ulonglong2*)&P[j * 64 + i0];
            ull vd0 = pack2(v0p[j], v0p[j]);
            ull vd1 = pack2(v1p[j], v1p[j]);
            o[0][0] = ffma2(vd0, a.x, o[0][0]); o[0][1] = ffma2(vd0, a.y, o[0][1]);
            o[1][0] = ffma2(vd1, a.x, o[1][0]); o[1][1] = ffma2(vd1, a.y, o[1][1]);
        }

        #pragma unroll
        for (int p = 0; p < 2; p++) {
            float2 e0 = unpack2(o[0][p]);
            float2 e1 = unpack2(o[1][p]);
            float r0[2] = {e0.x, e0.y};
            float r1[2] = {e1.x, e1.y};
            #pragma unroll
            for (int u = 0; u < 2; u++) {
                int il = i0 + p * 2 + u;
                int iglob = ig0 + il;
                float inv = s_inv[il];
                float out0 = r0[u] * inv - v0p[iglob];
                float out1 = r1[u] * inv - v1p[iglob];
                *(float2*)(g_act + ((size_t)b * TT + iglob) * DINP + h * KD + d0)
                    = make_float2(out0, out1);
            }
        }
    }
}

// ---------------------------------------------------------------------------
// Kernel 2: h1 = relu(act @ W1 + b1).  (4096,160)@(160,256)
// 512 threads, 16 rows/block, grid 256. W1 staged in smem, double-buffered
// panels of 8 k-rows; inner loop is pure LDS + FFMA2 (no LDG on dep path).
// Thread tile: 2 rows x 4 cols.
// ---------------------------------------------------------------------------
#define CKP 8
__global__ void __launch_bounds__(512) mlp1_kernel(
    const float* __restrict__ W1, const float* __restrict__ b1)
{
    __shared__ ull   s_a2[16 * DINP];      // 20KB dup'd activations
    __shared__ float s_w[CKP * HIDN];      // 8KB weight panel

    const int rbase = blockIdx.x * 16;
    const int t = threadIdx.x;

    {   // stage acts dup'd: 16*160 floats = 640 float4
        const float4* src = (const float4*)(g_act + (size_t)rbase * DINP);
        for (int n = t; n < 16 * DINP / 4; n += 512) {
            float4 v = src[n];
            ull* d = &s_a2[n * 4];
            d[0] = pack2(v.x, v.x); d[1] = pack2(v.y, v.y);
            d[2] = pack2(v.z, v.z); d[3] = pack2(v.w, v.w);
        }
    }

    const int ct = t & 63, rg = t >> 6;
    const int c0 = ct * 4, r0 = rg * 2;
    float4 bias = *(const float4*)(b1 + c0);
    ull acc[2][2];
    acc[0][0] = pack2(bias.x, bias.y); acc[0][1] = pack2(bias.z, bias.w);
    acc[1][0] = acc[0][0];             acc[1][1] = acc[0][1];

    // prefetch panel 0 (one float4 per thread: CKP*HIDN/4 = 512)
    float4 wv = *(const float4*)(W1 + (size_t)t * 4);

    const int NCH = DINP / CKP;   // 20
    for (int chunk = 0; chunk < NCH; chunk++) {
        __syncthreads();                       // panel consumed by all
        *(float4*)&s_w[t * 4] = wv;
        __syncthreads();
        if (chunk + 1 < NCH)                   // prefetch next during compute
            wv = *(const float4*)(W1 + (size_t)(chunk + 1) * CKP * HIDN + t * 4);
        const int kg0 = chunk * CKP;
        #pragma unroll
        for (int kk = 0; kk < CKP; kk++) {
            ulonglong2 w = *(const ulonglong2*)&s_w[kk * HIDN + c0];
            ull a0 = s_a2[(r0 + 0) * DINP + kg0 + kk];
            ull a1 = s_a2[(r0 + 1) * DINP + kg0 + kk];
            acc[0][0] = ffma2(a0, w.x, acc[0][0]);
            acc[0][1] = ffma2(a0, w.y, acc[0][1]);
            acc[1][0] = ffma2(a1, w.x, acc[1][0]);
            acc[1][1] = ffma2(a1, w.y, acc[1][1]);
        }
    }

    #pragma unroll
    for (int r = 0; r < 2; r++) {
        float2 p0 = unpack2(acc[r][0]), p1 = unpack2(acc[r][1]);
        float4 o = make_float4(fmaxf(p0.x, 0.f), fmaxf(p0.y, 0.f),
                               fmaxf(p1.x, 0.f), fmaxf(p1.y, 0.f));
        *(float4*)(g_h1 + ((size_t)(rbase + r0 + r)) * HIDN + c0) = o;
    }
}

// ---------------------------------------------------------------------------
// Kernel 3: h2 = relu(h1 @ W2 + b2); out = h2 @ Wo + bo (fused).
// Same structure as mlp1 (512 thr, 16 rows, smem-staged double-buffered W2).
// ---------------------------------------------------------------------------
__global__ void __launch_bounds__(512) mlp2_kernel(
    const float* __restrict__ W2, const float* __restrict__ b2,
    const float* __restrict__ Wo, const float* __restrict__ bo,
    float* __restrict__ out)
{
    __shared__ ull   s_a2[16 * HIDN];      // 32KB dup'd h1
    __shared__ float s_w[CKP * HIDN];      // 8KB weight panel
    __shared__ float s_red[16][2];

    const int rbase = blockIdx.x * 16;
    const int t = threadIdx.x;

    {   // stage h1 dup'd: 16*256 floats = 1024 float4
        const float4* src = (const float4*)(g_h1 + (size_t)rbase * HIDN);
        #pragma unroll
        for (int n = t; n < 16 * HIDN / 4; n += 512) {
            float4 v = src[n];
            ull* d = &s_a2[n * 4];
            d[0] = pack2(v.x, v.x); d[1] = pack2(v.y, v.y);
            d[2] = pack2(v.z, v.z); d[3] = pack2(v.w, v.w);
        }
    }

    const int ct = t & 63, rg = t >> 6;
    const int c0 = ct * 4, r0 = rg * 2;
    float4 bias = *(const float4*)(b2 + c0);
    ull acc[2][2];
    acc[0][0] = pack2(bias.x, bias.y); acc[0][1] = pack2(bias.z, bias.w);
    acc[1][0] = acc[0][0];             acc[1][1] = acc[0][1];

    float4 wv = *(const float4*)(W2 + (size_t)t * 4);

    const int NCH = HIDN / CKP;   // 32
    for (int chunk = 0; chunk < NCH; chunk++) {
        __syncthreads();
        *(float4*)&s_w[t * 4] = wv;
        __syncthreads();
        if (chunk + 1 < NCH)
            wv = *(const float4*)(W2 + (size_t)(chunk + 1) * CKP * HIDN + t * 4);
        const int kg0 = chunk * CKP;
        #pragma unroll
        for (int kk = 0; kk < CKP; kk++) {
            ulonglong2 w = *(const ulonglong2*)&s_w[kk * HIDN + c0];
            ull a0 = s_a2[(r0 + 0) * HIDN + kg0 + kk];
            ull a1 = s_a2[(r0 + 1) * HIDN + kg0 + kk];
            acc[0][0] = ffma2(a0, w.x, acc[0][0]);
            acc[0][1] = ffma2(a0, w.y, acc[0][1]);
            acc[1][0] = ffma2(a1, w.x, acc[1][0]);
            acc[1][1] = ffma2(a1, w.y, acc[1][1]);
        }
    }

    // relu then dot with Wo slice
    float4 wo = *(const float4*)(Wo + c0);
    float p[2];
    #pragma unroll
    for (int r = 0; r < 2; r++) {
        float2 p0 = unpack2(acc[r][0]), p1 = unpack2(acc[r][1]);
        float s = 0.f;
        s = fmaf(fmaxf(p0.x, 0.f), wo.x, s);
        s = fmaf(fmaxf(p0.y, 0.f), wo.y, s);
        s = fmaf(fmaxf(p1.x, 0.f), wo.z, s);
        s = fmaf(fmaxf(p1.y, 0.f), wo.w, s);
        p[r] = s;
    }
    // reduce: warp pair (2*rg, 2*rg+1) covers the 64 col-threads of rows r0..r0+1
    #pragma unroll
    for (int off = 16; off; off >>= 1) {
        #pragma unroll
        for (int r = 0; r < 2; r++)
            p[r] += __shfl_down_sync(0xffffffffu, p[r], off);
    }
    const int warp = t >> 5, lane = t & 31;
    if (lane == 0) {
        #pragma unroll
        for (int r = 0; r < 2; r++)
            s_red[r0 + r][warp & 1] = p[r];
    }
    __syncthreads();
    if (t < 16)
        out[rbase + t] = s_red[t][0] + s_red[t][1] + bo[0];
}

// ---------------------------------------------------------------------------
extern "C" void kernel_launch(void* const* d_in, const int* in_sizes, int n_in,
                              void* d_out, int out_size)
{
    (void)in_sizes; (void)n_in; (void)out_size;
    const float* state = (const float*)d_in[0];
    const float* Wq    = (const float*)d_in[1];
    const float* Wk    = (const float*)d_in[2];
    const float* Wv    = (const float*)d_in[3];
    const float* W1    = (const float*)d_in[4];
    const float* b1    = (const float*)d_in[5];
    const float* W2    = (const float*)d_in[6];
    const float* b2    = (const float*)d_in[7];
    const float* Wo    = (const float*)d_in[8];
    const float* bo    = (const float*)d_in[9];
    float* out = (float*)d_out;

    proj_kernel<<<384, 256>>>(state, Wq, Wk, Wv);
    attn_kernel<<<BB * HH * 2, 256>>>(state);
    mlp1_kernel<<<(BB * TT) / 16, 512>>>(W1, b1);
    mlp2_kernel<<<(BB * TT) / 16, 512>>>(W2, b2, Wo, bo, out);
}

// round 4
// speedup vs baseline: 1.0945x; 1.0945x over previous
#include <cuda_runtime.h>
#include <cstdint>

#define BB   32
#define TT   128
#define KD   32
#define HH   4
#define DINP 160
#define HIDN 256

// Scratch (static device globals; no allocation).
__device__ float g_qT[BB * HH * KD * TT];   // [b][h][kk][i]  2MB
__device__ float g_kT[BB * HH * KD * TT];   // [b][h][kk][j]
__device__ float g_vT[BB * HH * KD * TT];   // [b][h][d][j]
__device__ float g_act[BB * TT * DINP];     // [x | state]  4096 x 160
__device__ float g_h1[BB * TT * HIDN];      // hidden1     4096 x 256

typedef unsigned long long ull;

__device__ __forceinline__ ull ffma2(ull a, ull b, ull c) {
    ull d;
    asm("fma.rn.f32x2 %0, %1, %2, %3;" : "=l"(d) : "l"(a), "l"(b), "l"(c));
    return d;
}
__device__ __forceinline__ ull pack2(float x, float y) {
    ull r;
    asm("mov.b64 %0, {%1, %2};" : "=l"(r) : "f"(x), "f"(y));
    return r;
}
__device__ __forceinline__ float2 unpack2(ull v) {
    float x, y;
    asm("mov.b64 {%0, %1}, %2;" : "=f"(x), "=f"(y) : "l"(v));
    return make_float2(x, y);
}
__device__ __forceinline__ void cpa16(uint32_t dst_smem, const void* src) {
    asm volatile("cp.async.cg.shared.global [%0], [%1], 16;\n"
                 :: "r"(dst_smem), "l"(src) : "memory");
}
__device__ __forceinline__ void cpa_commit() {
    asm volatile("cp.async.commit_group;\n" ::: "memory");
}
template <int N>
__device__ __forceinline__ void cpa_wait() {
    asm volatile("cp.async.wait_group %0;\n" :: "n"(N) : "memory");
}

// ---------------------------------------------------------------------------
// Kernel 0: projections with transposed output.
// grid 384: blockIdx = rb (128 row-blocks of 32) + mat*128.
// ---------------------------------------------------------------------------
__global__ void __launch_bounds__(256) proj_kernel(
    const float* __restrict__ state,
    const float* __restrict__ Wq,
    const float* __restrict__ Wk,
    const float* __restrict__ Wv)
{
    __shared__ float sT[KD][36];       // stateT tile [c][r]
    __shared__ float Ws[KD * 128];     // W rows [k][c]

    const int bx  = blockIdx.x;
    const int rb  = bx & 127;
    const int mat = bx >> 7;
    const float* W = (mat == 0) ? Wq : (mat == 1) ? Wk : Wv;
    float* dstBase = (mat == 0) ? g_qT : (mat == 1) ? g_kT : g_vT;
    const int row0 = rb * 32;
    const int t = threadIdx.x;

    {   // stage W (32x128)
        const float4* src = (const float4*)W;
        float4* dst = (float4*)Ws;
        #pragma unroll
        for (int n = t; n < KD * 128 / 4; n += 256) dst[n] = src[n];
    }
    {   // stage state tile transposed
        int r = t >> 3, c0 = (t & 7) * 4;
        float4 v = *(const float4*)(state + (size_t)(row0 + r) * KD + c0);
        sT[c0 + 0][r] = v.x; sT[c0 + 1][r] = v.y;
        sT[c0 + 2][r] = v.z; sT[c0 + 3][r] = v.w;
    }
    __syncthreads();

    const int rg = t >> 5, cg = t & 31;
    const int r0 = rg * 4, c0 = cg * 4;
    ull acc[4][2];
    #pragma unroll
    for (int r = 0; r < 4; r++) { acc[r][0] = 0ull; acc[r][1] = 0ull; }

    #pragma unroll 8
    for (int k = 0; k < KD; k++) {
        float4 a4 = *(const float4*)&sT[k][r0];
        ulonglong2 b2 = *(const ulonglong2*)(Ws + k * 128 + c0);
        ull ad;
        ad = pack2(a4.x, a4.x); acc[0][0] = ffma2(ad, b2.x, acc[0][0]); acc[0][1] = ffma2(ad, b2.y, acc[0][1]);
        ad = pack2(a4.y, a4.y); acc[1][0] = ffma2(ad, b2.x, acc[1][0]); acc[1][1] = ffma2(ad, b2.y, acc[1][1]);
        ad = pack2(a4.z, a4.z); acc[2][0] = ffma2(ad, b2.x, acc[2][0]); acc[2][1] = ffma2(ad, b2.y, acc[2][1]);
        ad = pack2(a4.w, a4.w); acc[3][0] = ffma2(ad, b2.x, acc[3][0]); acc[3][1] = ffma2(ad, b2.y, acc[3][1]);
    }

    // transposed store
    const int b  = row0 >> 7;
    const int i0 = (row0 & 127) + r0;
    float cs[4][4];
    #pragma unroll
    for (int r = 0; r < 4; r++) {
        float2 p0 = unpack2(acc[r][0]), p1 = unpack2(acc[r][1]);
        cs[r][0] = p0.x; cs[r][1] = p0.y; cs[r][2] = p1.x; cs[r][3] = p1.y;
    }
    #pragma unroll
    for (int cc = 0; cc < 4; cc++) {
        int c = c0 + cc;
        int h = c >> 5, kk = c & 31;
        float4 o = make_float4(cs[0][cc], cs[1][cc], cs[2][cc], cs[3][cc]);
        *(float4*)(dstBase + ((size_t)((b * HH + h) * KD + kk)) * TT + i0) = o;
    }
}

// ---------------------------------------------------------------------------
// Kernel 1: masked attention for 64 query rows of one (b,h).
// grid 256 = (b, h, ihalf). Scores transposed in smem P[j][i].
// ---------------------------------------------------------------------------
__global__ void __launch_bounds__(256, 2) attn_kernel(const float* __restrict__ state)
{
    __shared__ float P[TT * 64];       // [j][i]  32KB
    __shared__ float s_mx[4][64];
    __shared__ float s_sm[4][64];
    __shared__ float s_inv[64];

    const int bx = blockIdx.x;
    const int b = bx >> 3, h = (bx >> 1) & 3, ihalf = bx & 1;
    const int t = threadIdx.x;
    const int ig0 = ihalf * 64;
    const float* QT = g_qT + (size_t)((b * HH + h) * KD) * TT;
    const float* KT = g_kT + (size_t)((b * HH + h) * KD) * TT;
    const float* VT = g_vT + (size_t)((b * HH + h) * KD) * TT;

    // ---- GEMM1: S^T[j][i] = K[j]·Q[i]; tile 8i x 4j
    {
        const int ig = t >> 5, jg = t & 31;
        const int i0 = ig * 8, j0 = jg * 4;
        ull acc[4][4];
        #pragma unroll
        for (int c = 0; c < 4; c++)
            #pragma unroll
            for (int p = 0; p < 4; p++) acc[c][p] = 0ull;

        #pragma unroll 4
        for (int kk = 0; kk < KD; kk++) {
            const float* qrow = QT + kk * TT + ig0 + i0;
            ulonglong2 a01 = *(const ulonglong2*)qrow;
            ulonglong2 a23 = *(const ulonglong2*)(qrow + 4);
            float4 bj = *(const float4*)(KT + kk * TT + j0);
            ull bd;
            bd = pack2(bj.x, bj.x);
            acc[0][0] = ffma2(bd, a01.x, acc[0][0]); acc[0][1] = ffma2(bd, a01.y, acc[0][1]);
            acc[0][2] = ffma2(bd, a23.x, acc[0][2]); acc[0][3] = ffma2(bd, a23.y, acc[0][3]);
            bd = pack2(bj.y, bj.y);
            acc[1][0] = ffma2(bd, a01.x, acc[1][0]); acc[1][1] = ffma2(bd, a01.y, acc[1][1]);
            acc[1][2] = ffma2(bd, a23.x, acc[1][2]); acc[1][3] = ffma2(bd, a23.y, acc[1][3]);
            bd = pack2(bj.z, bj.z);
            acc[2][0] = ffma2(bd, a01.x, acc[2][0]); acc[2][1] = ffma2(bd, a01.y, acc[2][1]);
            acc[2][2] = ffma2(bd, a23.x, acc[2][2]); acc[2][3] = ffma2(bd, a23.y, acc[2][3]);
            bd = pack2(bj.w, bj.w);
            acc[3][0] = ffma2(bd, a01.x, acc[3][0]); acc[3][1] = ffma2(bd, a01.y, acc[3][1]);
            acc[3][2] = ffma2(bd, a23.x, acc[3][2]); acc[3][3] = ffma2(bd, a23.y, acc[3][3]);
        }

        #pragma unroll
        for (int c = 0; c < 4; c++) {
            int jglob = j0 + c;
            int rd = jglob - ig0 - i0;          // diag position within my 8 i's
            if (rd >= 0 && rd < 8) {
                int p = rd >> 1, hi = rd & 1;
                float2 v = unpack2(acc[c][p]);
                if (hi) v.y = -1e30f; else v.x = -1e30f;
                acc[c][p] = pack2(v.x, v.y);
            }
            ull* dst = (ull*)&P[jglob * 64 + i0];
            dst[0] = acc[c][0]; dst[1] = acc[c][1];
            dst[2] = acc[c][2]; dst[3] = acc[c][3];
        }
    }
    __syncthreads();

    // ---- softmax (over j) on P, in place
    {
        const float scale = 0.17677669529663687f;   // 1/sqrt(32)
        const int i = t & 63, q = t >> 6;
        float mx = -1e30f;
        #pragma unroll 8
        for (int jj = 0; jj < 32; jj++)
            mx = fmaxf(mx, P[(q * 32 + jj) * 64 + i]);
        s_mx[q][i] = mx;
        __syncthreads();
        float m = fmaxf(fmaxf(s_mx[0][i], s_mx[1][i]), fmaxf(s_mx[2][i], s_mx[3][i]));
        float sum = 0.f;
        #pragma unroll 8
        for (int jj = 0; jj < 32; jj++) {
            int idx = (q * 32 + jj) * 64 + i;
            float e = __expf((P[idx] - m) * scale);
            P[idx] = e;
            sum += e;
        }
        s_sm[q][i] = sum;
    }
    // state copy into concat tail (no smem dependency)
    {
        #pragma unroll
        for (int n2 = t; n2 < 512; n2 += 256) {
            int r = n2 >> 3, c = n2 & 7;
            size_t row = (size_t)b * TT + ig0 + r;
            g_act[row * DINP + 4 * KD + h * 8 + c] = state[row * KD + h * 8 + c];
        }
    }
    __syncthreads();
    if (t < 64)
        s_inv[t] = 1.f / (s_sm[0][t] + s_sm[1][t] + s_sm[2][t] + s_sm[3][t]);
    __syncthreads();

    // ---- GEMM2: O[i][d] = sum_j P[j][i] * V[j][d]; tile 4i x 2d
    {
        const int ig = t & 15, dg = t >> 4;
        const int i0 = ig * 4, d0 = dg * 2;
        ull o[2][2];
        o[0][0] = 0ull; o[0][1] = 0ull; o[1][0] = 0ull; o[1][1] = 0ull;
        const float* v0p = VT + (size_t)d0 * TT;
        const float* v1p = VT + (size_t)(d0 + 1) * TT;

        #pragma unroll 4
        for (int j = 0; j < TT; j++) {
            ulonglong2 a = *(const ulonglong2*)&P[j * 64 + i0];
            ull vd0 = pack2(v0p[j], v0p[j]);
            ull vd1 = pack2(v1p[j], v1p[j]);
            o[0][0] = ffma2(vd0, a.x, o[0][0]); o[0][1] = ffma2(vd0, a.y, o[0][1]);
            o[1][0] = ffma2(vd1, a.x, o[1][0]); o[1][1] = ffma2(vd1, a.y, o[1][1]);
        }

        #pragma unroll
        for (int p = 0; p < 2; p++) {
            float2 e0 = unpack2(o[0][p]);
            float2 e1 = unpack2(o[1][p]);
            float r0[2] = {e0.x, e0.y};
            float r1[2] = {e1.x, e1.y};
            #pragma unroll
            for (int u = 0; u < 2; u++) {
                int il = i0 + p * 2 + u;
                int iglob = ig0 + il;
                float inv = s_inv[il];
                float out0 = r0[u] * inv - v0p[iglob];
                float out1 = r1[u] * inv - v1p[iglob];
                *(float2*)(g_act + ((size_t)b * TT + iglob) * DINP + h * KD + d0)
                    = make_float2(out0, out1);
            }
        }
    }
}

// ---------------------------------------------------------------------------
// MLP kernels: 16 rows/block, 128 threads, grid 256.
// Thread tile 4 rows x 8 cols. Activation tile transposed in smem
// (s_aT[k][row], broadcast LDS.128 = 4 rows), a-dup via register pack (alu
// MOV, off the crossbar). W panels (8 k-rows) cp.async double-buffered.
// ---------------------------------------------------------------------------
#define CKP 8

// ---- Kernel 2: h1 = relu(act @ W1 + b1) ----
__global__ void __launch_bounds__(128) mlp1_kernel(
    const float* __restrict__ W1, const float* __restrict__ b1)
{
    __shared__ float s_aT[DINP * 16];          // [k][row], 10KB
    __shared__ float s_w[2][CKP * HIDN];       // 2 x 8KB

    const int rbase = blockIdx.x * 16;
    const int t = threadIdx.x;
    const int c0 = (t & 31) * 8;
    const int r0 = (t >> 5) * 4;

    // stage activations transposed
    {
        const float4* src = (const float4*)(g_act + (size_t)rbase * DINP);
        for (int n = t; n < 16 * DINP / 4; n += 128) {
            float4 v = src[n];
            int row = (n * 4) / DINP, k = (n * 4) % DINP;
            s_aT[(k + 0) * 16 + row] = v.x;
            s_aT[(k + 1) * 16 + row] = v.y;
            s_aT[(k + 2) * 16 + row] = v.z;
            s_aT[(k + 3) * 16 + row] = v.w;
        }
    }

    const uint32_t wsm = (uint32_t)__cvta_generic_to_shared(&s_w[0][0]);

    // prologue: panel 0 -> buf 0
    #pragma unroll
    for (int u = 0; u < 4; u++)
        cpa16(wsm + (uint32_t)(t + u * 128) * 16,
              W1 + (size_t)(t + u * 128) * 4);
    cpa_commit();

    float4 bl = *(const float4*)(b1 + c0);
    float4 bh = *(const float4*)(b1 + c0 + 4);
    ull acc[4][4];
    #pragma unroll
    for (int r = 0; r < 4; r++) {
        acc[r][0] = pack2(bl.x, bl.y); acc[r][1] = pack2(bl.z, bl.w);
        acc[r][2] = pack2(bh.x, bh.y); acc[r][3] = pack2(bh.z, bh.w);
    }

    const int NCH = DINP / CKP;   // 20
    for (int ch = 0; ch < NCH; ch++) {
        if (ch + 1 < NCH) {
            const uint32_t dstb = wsm + (uint32_t)(((ch + 1) & 1) * CKP * HIDN) * 4;
            const float* srcb = W1 + (size_t)(ch + 1) * CKP * HIDN;
            #pragma unroll
            for (int u = 0; u < 4; u++)
                cpa16(dstb + (uint32_t)(t + u * 128) * 16,
                      srcb + (size_t)(t + u * 128) * 4);
            cpa_commit();
            cpa_wait<1>();
        } else {
            cpa_wait<0>();
        }
        __syncthreads();
        const float* wp = &s_w[ch & 1][0];
        const int kg0 = ch * CKP;
        #pragma unroll
        for (int kk = 0; kk < CKP; kk++) {
            ulonglong2 w01 = *(const ulonglong2*)(wp + kk * HIDN + c0);
            ulonglong2 w23 = *(const ulonglong2*)(wp + kk * HIDN + c0 + 4);
            float4 av = *(const float4*)&s_aT[(kg0 + kk) * 16 + r0];
            ull ad;
            ad = pack2(av.x, av.x);
            acc[0][0] = ffma2(ad, w01.x, acc[0][0]); acc[0][1] = ffma2(ad, w01.y, acc[0][1]);
            acc[0][2] = ffma2(ad, w23.x, acc[0][2]); acc[0][3] = ffma2(ad, w23.y, acc[0][3]);
            ad = pack2(av.y, av.y);
            acc[1][0] = ffma2(ad, w01.x, acc[1][0]); acc[1][1] = ffma2(ad, w01.y, acc[1][1]);
            acc[1][2] = ffma2(ad, w23.x, acc[1][2]); acc[1][3] = ffma2(ad, w23.y, acc[1][3]);
            ad = pack2(av.z, av.z);
            acc[2][0] = ffma2(ad, w01.x, acc[2][0]); acc[2][1] = ffma2(ad, w01.y, acc[2][1]);
            acc[2][2] = ffma2(ad, w23.x, acc[2][2]); acc[2][3] = ffma2(ad, w23.y, acc[2][3]);
            ad = pack2(av.w, av.w);
            acc[3][0] = ffma2(ad, w01.x, acc[3][0]); acc[3][1] = ffma2(ad, w01.y, acc[3][1]);
            acc[3][2] = ffma2(ad, w23.x, acc[3][2]); acc[3][3] = ffma2(ad, w23.y, acc[3][3]);
        }
        __syncthreads();
    }

    #pragma unroll
    for (int r = 0; r < 4; r++) {
        float2 p0 = unpack2(acc[r][0]), p1 = unpack2(acc[r][1]);
        float2 p2 = unpack2(acc[r][2]), p3 = unpack2(acc[r][3]);
        float* orow = g_h1 + ((size_t)(rbase + r0 + r)) * HIDN + c0;
        *(float4*)orow = make_float4(fmaxf(p0.x, 0.f), fmaxf(p0.y, 0.f),
                                     fmaxf(p1.x, 0.f), fmaxf(p1.y, 0.f));
        *(float4*)(orow + 4) = make_float4(fmaxf(p2.x, 0.f), fmaxf(p2.y, 0.f),
                                           fmaxf(p3.x, 0.f), fmaxf(p3.y, 0.f));
    }
}

// ---- Kernel 3: h2 = relu(h1 @ W2 + b2); out = h2 @ Wo + bo (fused) ----
__global__ void __launch_bounds__(128) mlp2_kernel(
    const float* __restrict__ W2, const float* __restrict__ b2,
    const float* __restrict__ Wo, const float* __restrict__ bo,
    float* __restrict__ out)
{
    __shared__ float s_aT[HIDN * 16];          // [k][row], 16KB
    __shared__ float s_w[2][CKP * HIDN];       // 2 x 8KB

    const int rbase = blockIdx.x * 16;
    const int t = threadIdx.x;
    const int c0 = (t & 31) * 8;
    const int r0 = (t >> 5) * 4;

    // stage h1 transposed
    {
        const float4* src = (const float4*)(g_h1 + (size_t)rbase * HIDN);
        #pragma unroll
        for (int n = t; n < 16 * HIDN / 4; n += 128) {
            float4 v = src[n];
            int row = n >> 6, k = (n & 63) * 4;
            s_aT[(k + 0) * 16 + row] = v.x;
            s_aT[(k + 1) * 16 + row] = v.y;
            s_aT[(k + 2) * 16 + row] = v.z;
            s_aT[(k + 3) * 16 + row] = v.w;
        }
    }

    const uint32_t wsm = (uint32_t)__cvta_generic_to_shared(&s_w[0][0]);

    #pragma unroll
    for (int u = 0; u < 4; u++)
        cpa16(wsm + (uint32_t)(t + u * 128) * 16,
              W2 + (size_t)(t + u * 128) * 4);
    cpa_commit();

    float4 bl = *(const float4*)(b2 + c0);
    float4 bh = *(const float4*)(b2 + c0 + 4);
    ull acc[4][4];
    #pragma unroll
    for (int r = 0; r < 4; r++) {
        acc[r][0] = pack2(bl.x, bl.y); acc[r][1] = pack2(bl.z, bl.w);
        acc[r][2] = pack2(bh.x, bh.y); acc[r][3] = pack2(bh.z, bh.w);
    }

    const int NCH = HIDN / CKP;   // 32
    for (int ch = 0; ch < NCH; ch++) {
        if (ch + 1 < NCH) {
            const uint32_t dstb = wsm + (uint32_t)(((ch + 1) & 1) * CKP * HIDN) * 4;
            const float* srcb = W2 + (size_t)(ch + 1) * CKP * HIDN;
            #pragma unroll
            for (int u = 0; u < 4; u++)
                cpa16(dstb + (uint32_t)(t + u * 128) * 16,
                      srcb + (size_t)(t + u * 128) * 4);
            cpa_commit();
            cpa_wait<1>();
        } else {
            cpa_wait<0>();
        }
        __syncthreads();
        const float* wp = &s_w[ch & 1][0];
        const int kg0 = ch * CKP;
        #pragma unroll
        for (int kk = 0; kk < CKP; kk++) {
            ulonglong2 w01 = *(const ulonglong2*)(wp + kk * HIDN + c0);
            ulonglong2 w23 = *(const ulonglong2*)(wp + kk * HIDN + c0 + 4);
            float4 av = *(const float4*)&s_aT[(kg0 + kk) * 16 + r0];
            ull ad;
            ad = pack2(av.x, av.x);
            acc[0][0] = ffma2(ad, w01.x, acc[0][0]); acc[0][1] = ffma2(ad, w01.y, acc[0][1]);
            acc[0][2] = ffma2(ad, w23.x, acc[0][2]); acc[0][3] = ffma2(ad, w23.y, acc[0][3]);
            ad = pack2(av.y, av.y);
            acc[1][0] = ffma2(ad, w01.x, acc[1][0]); acc[1][1] = ffma2(ad, w01.y, acc[1][1]);
            acc[1][2] = ffma2(ad, w23.x, acc[1][2]); acc[1][3] = ffma2(ad, w23.y, acc[1][3]);
            ad = pack2(av.z, av.z);
            acc[2][0] = ffma2(ad, w01.x, acc[2][0]); acc[2][1] = ffma2(ad, w01.y, acc[2][1]);
            acc[2][2] = ffma2(ad, w23.x, acc[2][2]); acc[2][3] = ffma2(ad, w23.y, acc[2][3]);
            ad = pack2(av.w, av.w);
            acc[3][0] = ffma2(ad, w01.x, acc[3][0]); acc[3][1] = ffma2(ad, w01.y, acc[3][1]);
            acc[3][2] = ffma2(ad, w23.x, acc[3][2]); acc[3][3] = ffma2(ad, w23.y, acc[3][3]);
        }
        __syncthreads();
    }

    // relu + dot with Wo slice; one warp spans all 256 columns -> pure shfl
    float4 wl = *(const float4*)(Wo + c0);
    float4 wh = *(const float4*)(Wo + c0 + 4);
    float p[4];
    #pragma unroll
    for (int r = 0; r < 4; r++) {
        float2 p0 = unpack2(acc[r][0]), p1 = unpack2(acc[r][1]);
        float2 p2 = unpack2(acc[r][2]), p3 = unpack2(acc[r][3]);
        float s = 0.f;
        s = fmaf(fmaxf(p0.x, 0.f), wl.x, s);
        s = fmaf(fmaxf(p0.y, 0.f), wl.y, s);
        s = fmaf(fmaxf(p1.x, 0.f), wl.z, s);
        s = fmaf(fmaxf(p1.y, 0.f), wl.w, s);
        s = fmaf(fmaxf(p2.x, 0.f), wh.x, s);
        s = fmaf(fmaxf(p2.y, 0.f), wh.y, s);
        s = fmaf(fmaxf(p3.x, 0.f), wh.z, s);
        s = fmaf(fmaxf(p3.y, 0.f), wh.w, s);
        p[r] = s;
    }
    #pragma unroll
    for (int off = 16; off; off >>= 1) {
        #pragma unroll
        for (int r = 0; r < 4; r++)
            p[r] += __shfl_down_sync(0xffffffffu, p[r], off);
    }
    if ((t & 31) == 0) {
        float bv = bo[0];
        #pragma unroll
        for (int r = 0; r < 4; r++)
            out[rbase + r0 + r] = p[r] + bv;
    }
}

// ---------------------------------------------------------------------------
extern "C" void kernel_launch(void* const* d_in, const int* in_sizes, int n_in,
                              void* d_out, int out_size)
{
    (void)in_sizes; (void)n_in; (void)out_size;
    const float* state = (const float*)d_in[0];
    const float* Wq    = (const float*)d_in[1];
    const float* Wk    = (const float*)d_in[2];
    const float* Wv    = (const float*)d_in[3];
    const float* W1    = (const float*)d_in[4];
    const float* b1    = (const float*)d_in[5];
    const float* W2    = (const float*)d_in[6];
    const float* b2    = (const float*)d_in[7];
    const float* Wo    = (const float*)d_in[8];
    const float* bo    = (const float*)d_in[9];
    float* out = (float*)d_out;

    proj_kernel<<<384, 256>>>(state, Wq, Wk, Wv);
    attn_kernel<<<BB * HH * 2, 256>>>(state);
    mlp1_kernel<<<(BB * TT) / 16, 128>>>(W1, b1);
    mlp2_kernel<<<(BB * TT) / 16, 128>>>(W2, b2, Wo, bo, out);
}

// round 5
// speedup vs baseline: 1.2603x; 1.1514x over previous
#include <cuda_runtime.h>
#include <cstdint>

#define BB   32
#define TT   128
#define KD   32
#define HH   4
#define DINP 160
#define HIDN 256

// Scratch (static device globals; no allocation).
__device__ float g_qT[BB * HH * KD * TT];   // [b][h][kk][i]  2MB
__device__ float g_kT[BB * HH * KD * TT];   // [b][h][kk][j]
__device__ float g_vT[BB * HH * KD * TT];   // [b][h][d][j]
__device__ float g_act[BB * TT * DINP];     // [x | state]  4096 x 160

typedef unsigned long long ull;

__device__ __forceinline__ ull ffma2(ull a, ull b, ull c) {
    ull d;
    asm("fma.rn.f32x2 %0, %1, %2, %3;" : "=l"(d) : "l"(a), "l"(b), "l"(c));
    return d;
}
__device__ __forceinline__ ull pack2(float x, float y) {
    ull r;
    asm("mov.b64 %0, {%1, %2};" : "=l"(r) : "f"(x), "f"(y));
    return r;
}
__device__ __forceinline__ float2 unpack2(ull v) {
    float x, y;
    asm("mov.b64 {%0, %1}, %2;" : "=f"(x), "=f"(y) : "l"(v));
    return make_float2(x, y);
}
__device__ __forceinline__ void cpa16(uint32_t dst_smem, const void* src) {
    asm volatile("cp.async.cg.shared.global [%0], [%1], 16;\n"
                 :: "r"(dst_smem), "l"(src) : "memory");
}
__device__ __forceinline__ void cpa_commit() {
    asm volatile("cp.async.commit_group;\n" ::: "memory");
}
template <int N>
__device__ __forceinline__ void cpa_wait() {
    asm volatile("cp.async.wait_group %0;\n" :: "n"(N) : "memory");
}

// ---------------------------------------------------------------------------
// Kernel 0: projections with transposed output + state tail copy into g_act.
// grid 384: blockIdx = rb (128 row-blocks of 32) + mat*128.
// ---------------------------------------------------------------------------
__global__ void __launch_bounds__(256) proj_kernel(
    const float* __restrict__ state,
    const float* __restrict__ Wq,
    const float* __restrict__ Wk,
    const float* __restrict__ Wv)
{
    __shared__ float sT[KD][36];       // stateT tile [c][r]
    __shared__ float Ws[KD * 128];     // W rows [k][c]

    const int bx  = blockIdx.x;
    const int rb  = bx & 127;
    const int mat = bx >> 7;
    const float* W = (mat == 0) ? Wq : (mat == 1) ? Wk : Wv;
    float* dstBase = (mat == 0) ? g_qT : (mat == 1) ? g_kT : g_vT;
    const int row0 = rb * 32;
    const int t = threadIdx.x;

    {   // stage W (32x128)
        const float4* src = (const float4*)W;
        float4* dst = (float4*)Ws;
        #pragma unroll
        for (int n = t; n < KD * 128 / 4; n += 256) dst[n] = src[n];
    }
    {   // stage state tile transposed; mat-0 blocks also copy the concat tail
        int r = t >> 3, c0 = (t & 7) * 4;
        float4 v = *(const float4*)(state + (size_t)(row0 + r) * KD + c0);
        sT[c0 + 0][r] = v.x; sT[c0 + 1][r] = v.y;
        sT[c0 + 2][r] = v.z; sT[c0 + 3][r] = v.w;
        if (mat == 0)
            *(float4*)(g_act + (size_t)(row0 + r) * DINP + 4 * KD + c0) = v;
    }
    __syncthreads();

    const int rg = t >> 5, cg = t & 31;
    const int r0 = rg * 4, c0 = cg * 4;
    ull acc[4][2];
    #pragma unroll
    for (int r = 0; r < 4; r++) { acc[r][0] = 0ull; acc[r][1] = 0ull; }

    #pragma unroll 8
    for (int k = 0; k < KD; k++) {
        float4 a4 = *(const float4*)&sT[k][r0];
        ulonglong2 b2 = *(const ulonglong2*)(Ws + k * 128 + c0);
        ull ad;
        ad = pack2(a4.x, a4.x); acc[0][0] = ffma2(ad, b2.x, acc[0][0]); acc[0][1] = ffma2(ad, b2.y, acc[0][1]);
        ad = pack2(a4.y, a4.y); acc[1][0] = ffma2(ad, b2.x, acc[1][0]); acc[1][1] = ffma2(ad, b2.y, acc[1][1]);
        ad = pack2(a4.z, a4.z); acc[2][0] = ffma2(ad, b2.x, acc[2][0]); acc[2][1] = ffma2(ad, b2.y, acc[2][1]);
        ad = pack2(a4.w, a4.w); acc[3][0] = ffma2(ad, b2.x, acc[3][0]); acc[3][1] = ffma2(ad, b2.y, acc[3][1]);
    }

    // transposed store
    const int b  = row0 >> 7;
    const int i0 = (row0 & 127) + r0;
    float cs[4][4];
    #pragma unroll
    for (int r = 0; r < 4; r++) {
        float2 p0 = unpack2(acc[r][0]), p1 = unpack2(acc[r][1]);
        cs[r][0] = p0.x; cs[r][1] = p0.y; cs[r][2] = p1.x; cs[r][3] = p1.y;
    }
    #pragma unroll
    for (int cc = 0; cc < 4; cc++) {
        int c = c0 + cc;
        int h = c >> 5, kk = c & 31;
        float4 o = make_float4(cs[0][cc], cs[1][cc], cs[2][cc], cs[3][cc]);
        *(float4*)(dstBase + ((size_t)((b * HH + h) * KD + kk)) * TT + i0) = o;
    }
}

// ---------------------------------------------------------------------------
// Kernel 1: masked attention for 64 query rows of one (b,h).
// grid 256 = (b, h, ihalf). Scores transposed in smem P[j][i].
// ---------------------------------------------------------------------------
__global__ void __launch_bounds__(256, 2) attn_kernel()
{
    __shared__ float P[TT * 64];       // [j][i]  32KB
    __shared__ float s_mx[4][64];
    __shared__ float s_sm[4][64];
    __shared__ float s_inv[64];

    const int bx = blockIdx.x;
    const int b = bx >> 3, h = (bx >> 1) & 3, ihalf = bx & 1;
    const int t = threadIdx.x;
    const int ig0 = ihalf * 64;
    const float* QT = g_qT + (size_t)((b * HH + h) * KD) * TT;
    const float* KT = g_kT + (size_t)((b * HH + h) * KD) * TT;
    const float* VT = g_vT + (size_t)((b * HH + h) * KD) * TT;

    // ---- GEMM1: S^T[j][i] = K[j]·Q[i]; tile 8i x 4j
    {
        const int ig = t >> 5, jg = t & 31;
        const int i0 = ig * 8, j0 = jg * 4;
        ull acc[4][4];
        #pragma unroll
        for (int c = 0; c < 4; c++)
            #pragma unroll
            for (int p = 0; p < 4; p++) acc[c][p] = 0ull;

        #pragma unroll 4
        for (int kk = 0; kk < KD; kk++) {
            const float* qrow = QT + kk * TT + ig0 + i0;
            ulonglong2 a01 = *(const ulonglong2*)qrow;
            ulonglong2 a23 = *(const ulonglong2*)(qrow + 4);
            float4 bj = *(const float4*)(KT + kk * TT + j0);
            ull bd;
            bd = pack2(bj.x, bj.x);
            acc[0][0] = ffma2(bd, a01.x, acc[0][0]); acc[0][1] = ffma2(bd, a01.y, acc[0][1]);
            acc[0][2] = ffma2(bd, a23.x, acc[0][2]); acc[0][3] = ffma2(bd, a23.y, acc[0][3]);
            bd = pack2(bj.y, bj.y);
            acc[1][0] = ffma2(bd, a01.x, acc[1][0]); acc[1][1] = ffma2(bd, a01.y, acc[1][1]);
            acc[1][2] = ffma2(bd, a23.x, acc[1][2]); acc[1][3] = ffma2(bd, a23.y, acc[1][3]);
            bd = pack2(bj.z, bj.z);
            acc[2][0] = ffma2(bd, a01.x, acc[2][0]); acc[2][1] = ffma2(bd, a01.y, acc[2][1]);
            acc[2][2] = ffma2(bd, a23.x, acc[2][2]); acc[2][3] = ffma2(bd, a23.y, acc[2][3]);
            bd = pack2(bj.w, bj.w);
            acc[3][0] = ffma2(bd, a01.x, acc[3][0]); acc[3][1] = ffma2(bd, a01.y, acc[3][1]);
            acc[3][2] = ffma2(bd, a23.x, acc[3][2]); acc[3][3] = ffma2(bd, a23.y, acc[3][3]);
        }

        #pragma unroll
        for (int c = 0; c < 4; c++) {
            int jglob = j0 + c;
            int rd = jglob - ig0 - i0;          // diag position within my 8 i's
            if (rd >= 0 && rd < 8) {
                int p = rd >> 1, hi = rd & 1;
                float2 v = unpack2(acc[c][p]);
                if (hi) v.y = -1e30f; else v.x = -1e30f;
                acc[c][p] = pack2(v.x, v.y);
            }
            ull* dst = (ull*)&P[jglob * 64 + i0];
            dst[0] = acc[c][0]; dst[1] = acc[c][1];
            dst[2] = acc[c][2]; dst[3] = acc[c][3];
        }
    }
    __syncthreads();

    // ---- softmax (over j) on P, in place
    {
        const float scale = 0.17677669529663687f;   // 1/sqrt(32)
        const int i = t & 63, q = t >> 6;
        float mx = -1e30f;
        #pragma unroll 8
        for (int jj = 0; jj < 32; jj++)
            mx = fmaxf(mx, P[(q * 32 + jj) * 64 + i]);
        s_mx[q][i] = mx;
        __syncthreads();
        float m = fmaxf(fmaxf(s_mx[0][i], s_mx[1][i]), fmaxf(s_mx[2][i], s_mx[3][i]));
        float sum = 0.f;
        #pragma unroll 8
        for (int jj = 0; jj < 32; jj++) {
            int idx = (q * 32 + jj) * 64 + i;
            float e = __expf((P[idx] - m) * scale);
            P[idx] = e;
            sum += e;
        }
        s_sm[q][i] = sum;
    }
    __syncthreads();
    if (t < 64)
        s_inv[t] = 1.f / (s_sm[0][t] + s_sm[1][t] + s_sm[2][t] + s_sm[3][t]);
    __syncthreads();

    // ---- GEMM2: O[i][d] = sum_j P[j][i] * V[j][d]; tile 4i x 2d,
    //      j chunked by 4 so V comes in as LDG.128 along contiguous j.
    {
        const int ig = t & 15, dg = t >> 4;
        const int i0 = ig * 4, d0 = dg * 2;
        ull o[2][2];
        o[0][0] = 0ull; o[0][1] = 0ull; o[1][0] = 0ull; o[1][1] = 0ull;
        const float* v0p = VT + (size_t)d0 * TT;
        const float* v1p = v0p + TT;

        for (int j = 0; j < TT; j += 4) {
            float4 v40 = *(const float4*)(v0p + j);
            float4 v41 = *(const float4*)(v1p + j);
            float va0[4] = {v40.x, v40.y, v40.z, v40.w};
            float va1[4] = {v41.x, v41.y, v41.z, v41.w};
            #pragma unroll
            for (int u = 0; u < 4; u++) {
                ulonglong2 a = *(const ulonglong2*)&P[(j + u) * 64 + i0];
                ull vd0 = pack2(va0[u], va0[u]);
                ull vd1 = pack2(va1[u], va1[u]);
                o[0][0] = ffma2(vd0, a.x, o[0][0]); o[0][1] = ffma2(vd0, a.y, o[0][1]);
                o[1][0] = ffma2(vd1, a.x, o[1][0]); o[1][1] = ffma2(vd1, a.y, o[1][1]);
            }
        }

        #pragma unroll
        for (int p = 0; p < 2; p++) {
            float2 e0 = unpack2(o[0][p]);
            float2 e1 = unpack2(o[1][p]);
            float r0[2] = {e0.x, e0.y};
            float r1[2] = {e1.x, e1.y};
            #pragma unroll
            for (int u = 0; u < 2; u++) {
                int il = i0 + p * 2 + u;
                int iglob = ig0 + il;
                float inv = s_inv[il];
                float out0 = r0[u] * inv - v0p[iglob];
                float out1 = r1[u] * inv - v1p[iglob];
                *(float2*)(g_act + ((size_t)b * TT + iglob) * DINP + h * KD + d0)
                    = make_float2(out0, out1);
            }
        }
    }
}

// ---------------------------------------------------------------------------
// Kernel 2 (fused MLP): h1 = relu(act@W1+b1); h2 = relu(h1@W2+b2);
// out = h2@Wo + bo. 16 rows/block, 128 threads, grid 256.
// h1 lives only in smem. a-operands are warp-uniform scalar-LDS broadcasts;
// W panels (8 k-rows) cp.async double-buffered; tile 4 rows x 8 cols.
// ---------------------------------------------------------------------------
#define CKP 8
__global__ void __launch_bounds__(128) mlp_kernel(
    const float* __restrict__ W1, const float* __restrict__ b1,
    const float* __restrict__ W2, const float* __restrict__ b2,
    const float* __restrict__ Wo, const float* __restrict__ bo,
    float* __restrict__ out)
{
    __shared__ float s_a[16 * DINP];           // [row][k]  10KB
    __shared__ float s_h1[16 * HIDN];          // [row][k]  16KB
    __shared__ float s_w[2][CKP * HIDN];       // 2 x 8KB

    const int rbase = blockIdx.x * 16;
    const int t = threadIdx.x;
    const int c0 = (t & 31) * 8;
    const int r0 = (t >> 5) * 4;
    const uint32_t wsm = (uint32_t)__cvta_generic_to_shared(&s_w[0][0]);

    // prologue: W1 panel 0 -> buf 0 (async), act tile -> smem (sync loads)
    #pragma unroll
    for (int u = 0; u < 4; u++)
        cpa16(wsm + (uint32_t)(t + u * 128) * 16, W1 + (size_t)(t + u * 128) * 4);
    cpa_commit();
    {
        const float4* src = (const float4*)(g_act + (size_t)rbase * DINP);
        float4* dst = (float4*)s_a;
        #pragma unroll
        for (int n = t; n < 16 * DINP / 4; n += 128) dst[n] = src[n];
    }

    ull acc[4][4];
    {
        float4 bl = *(const float4*)(b1 + c0);
        float4 bh = *(const float4*)(b1 + c0 + 4);
        #pragma unroll
        for (int r = 0; r < 4; r++) {
            acc[r][0] = pack2(bl.x, bl.y); acc[r][1] = pack2(bl.z, bl.w);
            acc[r][2] = pack2(bh.x, bh.y); acc[r][3] = pack2(bh.z, bh.w);
        }
    }

    // ---- phase 1: k = 0..159 over W1
    const int NCH1 = DINP / CKP;   // 20
    for (int ch = 0; ch < NCH1; ch++) {
        if (ch + 1 < NCH1) {
            const uint32_t dstb = wsm + (uint32_t)(((ch + 1) & 1) * CKP * HIDN) * 4;
            const float* srcb = W1 + (size_t)(ch + 1) * CKP * HIDN;
            #pragma unroll
            for (int u = 0; u < 4; u++)
                cpa16(dstb + (uint32_t)(t + u * 128) * 16, srcb + (size_t)(t + u * 128) * 4);
            cpa_commit();
            cpa_wait<1>();
        } else {
            cpa_wait<0>();
        }
        __syncthreads();
        const float* wp = &s_w[ch & 1][0];
        const int kg0 = ch * CKP;
        #pragma unroll
        for (int kk = 0; kk < CKP; kk++) {
            ulonglong2 w01 = *(const ulonglong2*)(wp + kk * HIDN + c0);
            ulonglong2 w23 = *(const ulonglong2*)(wp + kk * HIDN + c0 + 4);
            ull ad;
            ad = pack2(s_a[(r0 + 0) * DINP + kg0 + kk], s_a[(r0 + 0) * DINP + kg0 + kk]);
            acc[0][0] = ffma2(ad, w01.x, acc[0][0]); acc[0][1] = ffma2(ad, w01.y, acc[0][1]);
            acc[0][2] = ffma2(ad, w23.x, acc[0][2]); acc[0][3] = ffma2(ad, w23.y, acc[0][3]);
            ad = pack2(s_a[(r0 + 1) * DINP + kg0 + kk], s_a[(r0 + 1) * DINP + kg0 + kk]);
            acc[1][0] = ffma2(ad, w01.x, acc[1][0]); acc[1][1] = ffma2(ad, w01.y, acc[1][1]);
            acc[1][2] = ffma2(ad, w23.x, acc[1][2]); acc[1][3] = ffma2(ad, w23.y, acc[1][3]);
            ad = pack2(s_a[(r0 + 2) * DINP + kg0 + kk], s_a[(r0 + 2) * DINP + kg0 + kk]);
            acc[2][0] = ffma2(ad, w01.x, acc[2][0]); acc[2][1] = ffma2(ad, w01.y, acc[2][1]);
            acc[2][2] = ffma2(ad, w23.x, acc[2][2]); acc[2][3] = ffma2(ad, w23.y, acc[2][3]);
            ad = pack2(s_a[(r0 + 3) * DINP + kg0 + kk], s_a[(r0 + 3) * DINP + kg0 + kk]);
            acc[3][0] = ffma2(ad, w01.x, acc[3][0]); acc[3][1] = ffma2(ad, w01.y, acc[3][1]);
            acc[3][2] = ffma2(ad, w23.x, acc[3][2]); acc[3][3] = ffma2(ad, w23.y, acc[3][3]);
        }
        __syncthreads();
    }

    // ---- relu -> s_h1 (conflict-free STS.128), prefetch W2 panel 0
    #pragma unroll
    for (int u = 0; u < 4; u++)
        cpa16(wsm + (uint32_t)(t + u * 128) * 16, W2 + (size_t)(t + u * 128) * 4);
    cpa_commit();
    #pragma unroll
    for (int r = 0; r < 4; r++) {
        float2 p0 = unpack2(acc[r][0]), p1 = unpack2(acc[r][1]);
        float2 p2 = unpack2(acc[r][2]), p3 = unpack2(acc[r][3]);
        float* hrow = s_h1 + (r0 + r) * HIDN + c0;
        *(float4*)hrow = make_float4(fmaxf(p0.x, 0.f), fmaxf(p0.y, 0.f),
                                     fmaxf(p1.x, 0.f), fmaxf(p1.y, 0.f));
        *(float4*)(hrow + 4) = make_float4(fmaxf(p2.x, 0.f), fmaxf(p2.y, 0.f),
                                           fmaxf(p3.x, 0.f), fmaxf(p3.y, 0.f));
    }
    {
        float4 bl = *(const float4*)(b2 + c0);
        float4 bh = *(const float4*)(b2 + c0 + 4);
        #pragma unroll
        for (int r = 0; r < 4; r++) {
            acc[r][0] = pack2(bl.x, bl.y); acc[r][1] = pack2(bl.z, bl.w);
            acc[r][2] = pack2(bh.x, bh.y); acc[r][3] = pack2(bh.z, bh.w);
        }
    }
    __syncthreads();

    // ---- phase 2: k = 0..255 over W2, reading s_h1
    const int NCH2 = HIDN / CKP;   // 32
    for (int ch = 0; ch < NCH2; ch++) {
        if (ch + 1 < NCH2) {
            const uint32_t dstb = wsm + (uint32_t)(((ch + 1) & 1) * CKP * HIDN) * 4;
            const float* srcb = W2 + (size_t)(ch + 1) * CKP * HIDN;
            #pragma unroll
            for (int u = 0; u < 4; u++)
                cpa16(dstb + (uint32_t)(t + u * 128) * 16, srcb + (size_t)(t + u * 128) * 4);
            cpa_commit();
            cpa_wait<1>();
        } else {
            cpa_wait<0>();
        }
        __syncthreads();
        const float* wp = &s_w[ch & 1][0];
        const int kg0 = ch * CKP;
        #pragma unroll
        for (int kk = 0; kk < CKP; kk++) {
            ulonglong2 w01 = *(const ulonglong2*)(wp + kk * HIDN + c0);
            ulonglong2 w23 = *(const ulonglong2*)(wp + kk * HIDN + c0 + 4);
            ull ad;
            ad = pack2(s_h1[(r0 + 0) * HIDN + kg0 + kk], s_h1[(r0 + 0) * HIDN + kg0 + kk]);
            acc[0][0] = ffma2(ad, w01.x, acc[0][0]); acc[0][1] = ffma2(ad, w01.y, acc[0][1]);
            acc[0][2] = ffma2(ad, w23.x, acc[0][2]); acc[0][3] = ffma2(ad, w23.y, acc[0][3]);
            ad = pack2(s_h1[(r0 + 1) * HIDN + kg0 + kk], s_h1[(r0 + 1) * HIDN + kg0 + kk]);
            acc[1][0] = ffma2(ad, w01.x, acc[1][0]); acc[1][1] = ffma2(ad, w01.y, acc[1][1]);
            acc[1][2] = ffma2(ad, w23.x, acc[1][2]); acc[1][3] = ffma2(ad, w23.y, acc[1][3]);
            ad = pack2(s_h1[(r0 + 2) * HIDN + kg0 + kk], s_h1[(r0 + 2) * HIDN + kg0 + kk]);
            acc[2][0] = ffma2(ad, w01.x, acc[2][0]); acc[2][1] = ffma2(ad, w01.y, acc[2][1]);
            acc[2][2] = ffma2(ad, w23.x, acc[2][2]); acc[2][3] = ffma2(ad, w23.y, acc[2][3]);
            ad = pack2(s_h1[(r0 + 3) * HIDN + kg0 + kk], s_h1[(r0 + 3) * HIDN + kg0 + kk]);
            acc[3][0] = ffma2(ad, w01.x, acc[3][0]); acc[3][1] = ffma2(ad, w01.y, acc[3][1]);
            acc[3][2] = ffma2(ad, w23.x, acc[3][2]); acc[3][3] = ffma2(ad, w23.y, acc[3][3]);
        }
        __syncthreads();
    }

    // ---- relu + dot with Wo slice; one warp spans all 256 cols -> pure shfl
    float4 wl = *(const float4*)(Wo + c0);
    float4 wh = *(const float4*)(Wo + c0 + 4);
    float p[4];
    #pragma unroll
    for (int r = 0; r < 4; r++) {
        float2 p0 = unpack2(acc[r][0]), p1 = unpack2(acc[r][1]);
        float2 p2 = unpack2(acc[r][2]), p3 = unpack2(acc[r][3]);
        float s = 0.f;
        s = fmaf(fmaxf(p0.x, 0.f), wl.x, s);
        s = fmaf(fmaxf(p0.y, 0.f), wl.y, s);
        s = fmaf(fmaxf(p1.x, 0.f), wl.z, s);
        s = fmaf(fmaxf(p1.y, 0.f), wl.w, s);
        s = fmaf(fmaxf(p2.x, 0.f), wh.x, s);
        s = fmaf(fmaxf(p2.y, 0.f), wh.y, s);
        s = fmaf(fmaxf(p3.x, 0.f), wh.z, s);
        s = fmaf(fmaxf(p3.y, 0.f), wh.w, s);
        p[r] = s;
    }
    #pragma unroll
    for (int off = 16; off; off >>= 1) {
        #pragma unroll
        for (int r = 0; r < 4; r++)
            p[r] += __shfl_down_sync(0xffffffffu, p[r], off);
    }
    if ((t & 31) == 0) {
        float bv = bo[0];
        #pragma unroll
        for (int r = 0; r < 4; r++)
            out[rbase + r0 + r] = p[r] + bv;
    }
}

// ---------------------------------------------------------------------------
extern "C" void kernel_launch(void* const* d_in, const int* in_sizes, int n_in,
                              void* d_out, int out_size)
{
    (void)in_sizes; (void)n_in; (void)out_size;
    const float* state = (const float*)d_in[0];
    const float* Wq    = (const float*)d_in[1];
    const float* Wk    = (const float*)d_in[2];
    const float* Wv    = (const float*)d_in[3];
    const float* W1    = (const float*)d_in[4];
    const float* b1    = (const float*)d_in[5];
    const float* W2    = (const float*)d_in[6];
    const float* b2    = (const float*)d_in[7];
    const float* Wo    = (const float*)d_in[8];
    const float* bo    = (const float*)d_in[9];
    float* out = (float*)d_out;

    proj_kernel<<<384, 256>>>(state, Wq, Wk, Wv);
    attn_kernel<<<BB * HH * 2, 256>>>();
    mlp_kernel<<<(BB * TT) / 16, 128>>>(W1, b1, W2, b2, Wo, bo, out);
}